// round 1
// baseline (speedup 1.0000x reference)
#include <cuda_runtime.h>
#include <cuda_bf16.h>
#include <math.h>

// Problem constants
#define BATCH   4096
#define D1      200
#define NREL    500
#define M1      288      // FC1_LEN = OC*FW
#define OC      32
#define FW      9
#define WOUT    392
#define WIN     400
#define FCLEN   12544    // OC*WOUT
#define EPSBN   1e-5f

// ---------------- device scratch (no allocation allowed) ----------------
__device__ float g_a[WIN];             // a_i = s2_i * fc2_w[i]
__device__ float g_v[FCLEN];           // v[f] = sum_i a_i * fc_w[i,f]
__device__ float g_fc1T[D1 * M1];      // fc1_w transposed [200][288]
__device__ float g_Krel[NREL * M1];    // per-relation filters (with fc1 bias)
__device__ float g_q[NREL * WIN];      // q[r][t]
__device__ float g_Sq[NREL];           // sum_t q[r][t]
__device__ float g_scal[2];            // [0]=d_base, [1]=bn1 offset term

// ---------------- K0: fold bn2+fc2+fc_b into a[] and d_base -------------
__global__ void k0_fold(const float* __restrict__ bn2g, const float* __restrict__ bn2b,
                        const float* __restrict__ bn2m, const float* __restrict__ bn2v,
                        const float* __restrict__ fc2w, const float* __restrict__ fc2b,
                        const float* __restrict__ fcb) {
    __shared__ float red[512];
    int i = threadIdx.x;
    float term = 0.f;
    if (i < WIN) {
        float s2 = bn2g[i] * rsqrtf(bn2v[i] + EPSBN);
        float a  = s2 * fc2w[i];
        g_a[i] = a;
        term = (bn2b[i] - bn2m[i] * s2) * fc2w[i] + a * fcb[i];
    }
    red[i] = term;
    __syncthreads();
    for (int s = 256; s > 0; s >>= 1) {
        if (i < s) red[i] += red[i + s];
        __syncthreads();
    }
    if (i == 0) g_scal[0] = red[0] + fc2b[0];
}

// ---------------- K1: v[f] = sum_i a_i * fc_w[i,f]  (20MB sweep) --------
__global__ void k1_v(const float* __restrict__ fcw) {
    __shared__ float sa[WIN];
    for (int i = threadIdx.x; i < WIN; i += 256) sa[i] = g_a[i];
    __syncthreads();
    int f = blockIdx.x * 256 + threadIdx.x;
    if (f >= FCLEN) return;
    float acc = 0.f;
#pragma unroll 8
    for (int i = 0; i < WIN; i++)
        acc = fmaf(sa[i], fcw[i * FCLEN + f], acc);
    g_v[f] = acc;
}

// ---------------- K1b: bn1 offset term = sum_c (b1-m1*inv1)*sum_w v ----
__global__ void k1b_off(const float* __restrict__ bn1g, const float* __restrict__ bn1b,
                        const float* __restrict__ bn1m, const float* __restrict__ bn1v) {
    __shared__ float red[OC];
    int c = threadIdx.x >> 5, lane = threadIdx.x & 31;
    float s = 0.f;
    for (int t = lane; t < WOUT; t += 32) s += g_v[c * WOUT + t];
    for (int o = 16; o; o >>= 1) s += __shfl_down_sync(0xffffffffu, s, o);
    if (lane == 0) {
        float inv1 = bn1g[c] * rsqrtf(bn1v[c] + EPSBN);
        red[c] = (bn1b[c] - bn1m[c] * inv1) * s;
    }
    __syncthreads();
    if (threadIdx.x == 0) {
        float tot = 0.f;
        for (int i = 0; i < OC; i++) tot += red[i];
        g_scal[1] = tot;
    }
}

// ---------------- K2a: transpose fc1_w [288,200] -> [200,288] -----------
__global__ void k2a_tr(const float* __restrict__ fc1w) {
    __shared__ float tile[32][33];
    int d0 = blockIdx.x * 32, m0 = blockIdx.y * 32;
    int d = d0 + threadIdx.x, m = m0 + threadIdx.y;
    if (d < D1 && m < M1) tile[threadIdx.y][threadIdx.x] = fc1w[m * D1 + d];
    __syncthreads();
    int dd = d0 + threadIdx.y, mm = m0 + threadIdx.x;
    if (dd < D1 && mm < M1) g_fc1T[dd * M1 + mm] = tile[threadIdx.x][threadIdx.y];
}

// ---------------- K2b: K_rel[r,m] = R[r,:]·fc1_w[m,:] + fc1_b[m] --------
#define RCHUNK 16
__global__ void k2b_krel(const float* __restrict__ Rt, const float* __restrict__ fc1b) {
    __shared__ float sR[RCHUNK][D1];
    int m = threadIdx.x;          // 0..287
    int r0 = blockIdx.x * RCHUNK;
    for (int idx = threadIdx.x; idx < RCHUNK * D1; idx += M1) {
        int rr = idx / D1, d = idx % D1;
        int r = r0 + rr;
        sR[rr][d] = (r < NREL) ? Rt[r * D1 + d] : 0.f;
    }
    __syncthreads();
    float acc[RCHUNK];
#pragma unroll
    for (int rr = 0; rr < RCHUNK; rr++) acc[rr] = 0.f;
    for (int d = 0; d < D1; d++) {
        float w = g_fc1T[d * M1 + m];
#pragma unroll
        for (int rr = 0; rr < RCHUNK; rr++) acc[rr] = fmaf(w, sR[rr][d], acc[rr]);
    }
    float bm = fc1b[m];
#pragma unroll
    for (int rr = 0; rr < RCHUNK; rr++) {
        int r = r0 + rr;
        if (r < NREL) g_Krel[r * M1 + m] = acc[rr] + bm;
    }
}

// ---------------- K3: q[r][t] = sum_{o,j} Krel[r][o*9+j]*inv1_o*v[o,t-j] -
__global__ void k3_q(const float* __restrict__ bn1g, const float* __restrict__ bn1v) {
    __shared__ float sK[M1];
    __shared__ float sinv[OC];
    __shared__ float sv[8 * WOUT];   // 8-channel staging, 12.5KB
    __shared__ float red[16];
    int r = blockIdx.x, tid = threadIdx.x;
    for (int i = tid; i < M1; i += 512) sK[i] = g_Krel[r * M1 + i];
    if (tid < OC) sinv[tid] = bn1g[tid] * rsqrtf(bn1v[tid] + EPSBN);
    float acc = 0.f;
    int t = tid;
    for (int oc = 0; oc < 4; oc++) {
        __syncthreads();
        for (int i = tid; i < 8 * WOUT; i += 512) {
            int c = oc * 8 + i / WOUT;
            sv[i] = g_v[c * WOUT + (i % WOUT)] * sinv[c];
        }
        __syncthreads();
        if (t < WIN) {
#pragma unroll
            for (int o = 0; o < 8; o++) {
                int og = oc * 8 + o;
#pragma unroll
                for (int j = 0; j < FW; j++) {
                    int w = t - j;
                    if ((unsigned)w < (unsigned)WOUT)
                        acc = fmaf(sK[og * FW + j], sv[o * WOUT + w], acc);
                }
            }
        }
    }
    if (t < WIN) g_q[r * WIN + t] = acc;
    // block-reduce Sq[r]
    float s = (t < WIN) ? acc : 0.f;
    for (int o = 16; o; o >>= 1) s += __shfl_down_sync(0xffffffffu, s, o);
    if ((tid & 31) == 0) red[tid >> 5] = s;
    __syncthreads();
    if (tid == 0) {
        float tot = 0.f;
        for (int i = 0; i < 16; i++) tot += red[i];
        g_Sq[r] = tot;
    }
}

// ---------------- K4: main — gather + 400-dot + tanh --------------------
__global__ void k4_main(const int* __restrict__ e1i, const int* __restrict__ ri,
                        const int* __restrict__ e2i, const float* __restrict__ Et,
                        const float* __restrict__ bn0g, const float* __restrict__ bn0b,
                        const float* __restrict__ bn0m, const float* __restrict__ bn0v,
                        const float* __restrict__ bias, float* __restrict__ out) {
    int warp = threadIdx.x >> 5, lane = threadIdx.x & 31;
    int b = blockIdx.x * 8 + warp;
    if (b >= BATCH) return;
    int e1 = e1i[b], e2 = e2i[b], r = ri[b];
    const float* __restrict__ q  = g_q + r * WIN;
    const float* __restrict__ E1 = Et + (long)e1 * D1;
    const float* __restrict__ E2 = Et + (long)e2 * D1;
    float acc = 0.f;
    for (int t = lane; t < D1; t += 32) {
        acc = fmaf(E1[t], q[t], acc);
        acc = fmaf(E2[t], q[D1 + t], acc);
    }
    for (int o = 16; o; o >>= 1) acc += __shfl_down_sync(0xffffffffu, acc, o);
    if (lane == 0) {
        float s0 = bn0g[0] * rsqrtf(bn0v[0] + EPSBN);
        float z = s0 * acc + (bn0b[0] - bn0m[0] * s0) * g_Sq[r]
                + g_scal[0] + g_scal[1];
        out[b] = tanhf(z) + bias[0];
    }
}

// ---------------- launch ------------------------------------------------
extern "C" void kernel_launch(void* const* d_in, const int* in_sizes, int n_in,
                              void* d_out, int out_size) {
    const int*   e1_idx  = (const int*)  d_in[0];
    const int*   r_idx   = (const int*)  d_in[1];
    const int*   e2_idx  = (const int*)  d_in[2];
    const float* E_table = (const float*)d_in[3];
    const float* R_table = (const float*)d_in[4];
    const float* bn0g    = (const float*)d_in[5];
    const float* bn0b    = (const float*)d_in[6];
    const float* bn0m    = (const float*)d_in[7];
    const float* bn0v    = (const float*)d_in[8];
    const float* fc1w    = (const float*)d_in[9];
    const float* fc1b    = (const float*)d_in[10];
    const float* bn1g    = (const float*)d_in[11];
    const float* bn1b    = (const float*)d_in[12];
    const float* bn1m    = (const float*)d_in[13];
    const float* bn1v    = (const float*)d_in[14];
    const float* fcw     = (const float*)d_in[15];
    const float* fcb     = (const float*)d_in[16];
    const float* bn2g    = (const float*)d_in[17];
    const float* bn2b    = (const float*)d_in[18];
    const float* bn2m    = (const float*)d_in[19];
    const float* bn2v    = (const float*)d_in[20];
    const float* fc2w    = (const float*)d_in[21];
    const float* fc2b    = (const float*)d_in[22];
    const float* bias    = (const float*)d_in[23];
    float* out = (float*)d_out;

    k0_fold<<<1, 512>>>(bn2g, bn2b, bn2m, bn2v, fc2w, fc2b, fcb);
    k1_v<<<(FCLEN + 255) / 256, 256>>>(fcw);
    k1b_off<<<1, OC * 32>>>(bn1g, bn1b, bn1m, bn1v);
    k2a_tr<<<dim3((D1 + 31) / 32, (M1 + 31) / 32), dim3(32, 32)>>>(fc1w);
    k2b_krel<<<(NREL + RCHUNK - 1) / RCHUNK, M1>>>(R_table, fc1b);
    k3_q<<<NREL, 512>>>(bn1g, bn1v);
    k4_main<<<BATCH / 8, 256>>>(e1_idx, r_idx, e2_idx, E_table,
                                bn0g, bn0b, bn0m, bn0v, bias, out);
}

// round 2
// speedup vs baseline: 1.7307x; 1.7307x over previous
#include <cuda_runtime.h>
#include <cuda_bf16.h>
#include <math.h>

#define BATCH   4096
#define D1      200
#define NREL    500
#define M1      288      // OC*FW
#define OC      32
#define FW      9
#define WOUT    392
#define WIN     400
#define FCLEN   12544
#define EPSBN   1e-5f
#define NSPLIT  8
#define ILEN    50       // WIN / NSPLIT
#define FBLK    49       // FCLEN / 256

// ---------------- device scratch ----------------
__device__ float g_vp[NSPLIT * FCLEN];   // v partial sums
__device__ float g_Krel[NREL * M1];      // per-relation filters (+fc1 bias)
__device__ float g_Vmat[M1 * WIN];       // Vmat[m][t] = inv1_o * v[o][t-j]
__device__ float g_q[NREL * WIN];        // q table
__device__ float g_c1[OC];               // bn1 offset partials
__device__ float g_scal0;                // folded bn2/fc2/fc_b constant

// ======== K1: v partials (8-way i-split) + scal0 in spare block =========
__global__ void k1_v(const float* __restrict__ fcw,
                     const float* __restrict__ bn2g, const float* __restrict__ bn2b,
                     const float* __restrict__ bn2m, const float* __restrict__ bn2v,
                     const float* __restrict__ fc2w, const float* __restrict__ fc2b,
                     const float* __restrict__ fcb) {
    int tid = threadIdx.x;
    if (blockIdx.x == NSPLIT * FBLK) {       // scal0 block
        __shared__ float red[256];
        float t = 0.f;
        for (int i = tid; i < WIN; i += 256) {
            float s2 = bn2g[i] * rsqrtf(bn2v[i] + EPSBN);
            float a  = s2 * fc2w[i];
            t += (bn2b[i] - bn2m[i] * s2) * fc2w[i] + a * fcb[i];
        }
        red[tid] = t;
        __syncthreads();
        for (int s = 128; s; s >>= 1) { if (tid < s) red[tid] += red[tid + s]; __syncthreads(); }
        if (tid == 0) g_scal0 = red[0] + fc2b[0];
        return;
    }
    int isp = blockIdx.x / FBLK, fb = blockIdx.x % FBLK;
    __shared__ float sa[ILEN];
    if (tid < ILEN) {
        int i = isp * ILEN + tid;
        float s2 = bn2g[i] * rsqrtf(bn2v[i] + EPSBN);
        sa[tid] = s2 * fc2w[i];
    }
    __syncthreads();
    int f = fb * 256 + tid;
    const float* __restrict__ p = fcw + (size_t)isp * ILEN * FCLEN + f;
    float acc = 0.f;
#pragma unroll
    for (int ii = 0; ii < ILEN; ii++)
        acc = fmaf(sa[ii], p[(size_t)ii * FCLEN], acc);
    g_vp[isp * FCLEN + f] = acc;
}

// ======== GEMM1: Krel[500x288] = R[500x200] @ fc1w[288x200]^T + b =======
// 32x32 tile, 64 threads, 4x4 register tile, KC=8 (200 = 25*8 exact)
__global__ void gemm1_krel(const float* __restrict__ A,   // R  [500][200]
                           const float* __restrict__ Bw,  // fc1w [288][200]
                           const float* __restrict__ bias) {
    __shared__ float As[8][36];
    __shared__ float Bs[8][36];
    int tid = threadIdx.x;                 // 0..63
    int tx = tid & 7, ty = tid >> 3;
    int row0 = blockIdx.x * 32, col0 = blockIdx.y * 32;
    float acc[4][4] = {};
    for (int k0 = 0; k0 < 200; k0 += 8) {
#pragma unroll
        for (int l = 0; l < 4; l++) {
            int e = l * 64 + tid;          // 0..255
            int m = e >> 3, kk = e & 7;
            int gm = row0 + m;
            As[kk][m] = (gm < NREL) ? A[gm * 200 + k0 + kk] : 0.f;
            Bs[kk][m] = Bw[(col0 + m) * 200 + k0 + kk];  // col0+m < 288 always
        }
        __syncthreads();
#pragma unroll
        for (int kk = 0; kk < 8; kk++) {
            float4 a4 = *(const float4*)&As[kk][ty * 4];
            float4 b4 = *(const float4*)&Bs[kk][tx * 4];
            acc[0][0] = fmaf(a4.x, b4.x, acc[0][0]); acc[0][1] = fmaf(a4.x, b4.y, acc[0][1]);
            acc[0][2] = fmaf(a4.x, b4.z, acc[0][2]); acc[0][3] = fmaf(a4.x, b4.w, acc[0][3]);
            acc[1][0] = fmaf(a4.y, b4.x, acc[1][0]); acc[1][1] = fmaf(a4.y, b4.y, acc[1][1]);
            acc[1][2] = fmaf(a4.y, b4.z, acc[1][2]); acc[1][3] = fmaf(a4.y, b4.w, acc[1][3]);
            acc[2][0] = fmaf(a4.z, b4.x, acc[2][0]); acc[2][1] = fmaf(a4.z, b4.y, acc[2][1]);
            acc[2][2] = fmaf(a4.z, b4.z, acc[2][2]); acc[2][3] = fmaf(a4.z, b4.w, acc[2][3]);
            acc[3][0] = fmaf(a4.w, b4.x, acc[3][0]); acc[3][1] = fmaf(a4.w, b4.y, acc[3][1]);
            acc[3][2] = fmaf(a4.w, b4.z, acc[3][2]); acc[3][3] = fmaf(a4.w, b4.w, acc[3][3]);
        }
        __syncthreads();
    }
#pragma unroll
    for (int mi = 0; mi < 4; mi++) {
        int gm = row0 + ty * 4 + mi;
        if (gm < NREL) {
#pragma unroll
            for (int ni = 0; ni < 4; ni++) {
                int gn = col0 + tx * 4 + ni;
                g_Krel[gm * M1 + gn] = acc[mi][ni] + bias[gn];
            }
        }
    }
}

// ======== KV: build Vmat (fold v partials + inv1) + c1 partials =========
__global__ void kv_build(const float* __restrict__ bn1g, const float* __restrict__ bn1b,
                         const float* __restrict__ bn1m, const float* __restrict__ bn1v) {
    __shared__ float red[128];
    int m = blockIdx.x;                    // 0..287
    int o = m / FW, j = m % FW;
    int tid = threadIdx.x;
    float inv1 = bn1g[o] * rsqrtf(bn1v[o] + EPSBN);
    float vsum = 0.f;
    for (int t = tid; t < WIN; t += 128) {
        int w = t - j;
        float val = 0.f;
        if (w >= 0 && w < WOUT) {
            float s = 0.f;
#pragma unroll
            for (int sp = 0; sp < NSPLIT; sp++) s += g_vp[sp * FCLEN + o * WOUT + w];
            val = s;
            vsum += s;
        }
        g_Vmat[m * WIN + t] = val * inv1;
    }
    if (j == 0) {                          // this block saw all of channel o
        red[tid] = vsum;
        __syncthreads();
        for (int s = 64; s; s >>= 1) { if (tid < s) red[tid] += red[tid + s]; __syncthreads(); }
        if (tid == 0) g_c1[o] = (bn1b[o] - bn1m[o] * inv1) * red[0];
    }
}

// ======== GEMM2: q[500x400] = Krel[500x288] @ Vmat[288x400] =============
// 32x32 tile, 64 threads, 4x4 register tile, KC=8 (288 = 36*8 exact)
__global__ void gemm2_q() {
    __shared__ float As[8][36];
    __shared__ float Bs[8][36];
    int tid = threadIdx.x;
    int tx = tid & 7, ty = tid >> 3;
    int row0 = blockIdx.x * 32, col0 = blockIdx.y * 32;
    float acc[4][4] = {};
    for (int k0 = 0; k0 < M1; k0 += 8) {
#pragma unroll
        for (int l = 0; l < 4; l++) {
            int e = l * 64 + tid;
            {   // A: K-major pattern
                int am = e >> 3, akk = e & 7;
                int gm = row0 + am;
                As[akk][am] = (gm < NREL) ? g_Krel[gm * M1 + k0 + akk] : 0.f;
            }
            {   // B: N-major pattern
                int bkk = e >> 5, bn = e & 31;
                int gn = col0 + bn;
                Bs[bkk][bn] = (gn < WIN) ? g_Vmat[(k0 + bkk) * WIN + gn] : 0.f;
            }
        }
        __syncthreads();
#pragma unroll
        for (int kk = 0; kk < 8; kk++) {
            float4 a4 = *(const float4*)&As[kk][ty * 4];
            float4 b4 = *(const float4*)&Bs[kk][tx * 4];
            acc[0][0] = fmaf(a4.x, b4.x, acc[0][0]); acc[0][1] = fmaf(a4.x, b4.y, acc[0][1]);
            acc[0][2] = fmaf(a4.x, b4.z, acc[0][2]); acc[0][3] = fmaf(a4.x, b4.w, acc[0][3]);
            acc[1][0] = fmaf(a4.y, b4.x, acc[1][0]); acc[1][1] = fmaf(a4.y, b4.y, acc[1][1]);
            acc[1][2] = fmaf(a4.y, b4.z, acc[1][2]); acc[1][3] = fmaf(a4.y, b4.w, acc[1][3]);
            acc[2][0] = fmaf(a4.z, b4.x, acc[2][0]); acc[2][1] = fmaf(a4.z, b4.y, acc[2][1]);
            acc[2][2] = fmaf(a4.z, b4.z, acc[2][2]); acc[2][3] = fmaf(a4.z, b4.w, acc[2][3]);
            acc[3][0] = fmaf(a4.w, b4.x, acc[3][0]); acc[3][1] = fmaf(a4.w, b4.y, acc[3][1]);
            acc[3][2] = fmaf(a4.w, b4.z, acc[3][2]); acc[3][3] = fmaf(a4.w, b4.w, acc[3][3]);
        }
        __syncthreads();
    }
#pragma unroll
    for (int mi = 0; mi < 4; mi++) {
        int gm = row0 + ty * 4 + mi;
        if (gm < NREL) {
#pragma unroll
            for (int ni = 0; ni < 4; ni++) {
                int gn = col0 + tx * 4 + ni;
                if (gn < WIN) g_q[gm * WIN + gn] = acc[mi][ni];
            }
        }
    }
}

// ======== K4: gather + 400-dot (bn0 + Sq folded in) + tanh ==============
__global__ void k4_main(const int* __restrict__ e1i, const int* __restrict__ ri,
                        const int* __restrict__ e2i, const float* __restrict__ Et,
                        const float* __restrict__ bn0g, const float* __restrict__ bn0b,
                        const float* __restrict__ bn0m, const float* __restrict__ bn0v,
                        const float* __restrict__ bias, float* __restrict__ out) {
    int warp = threadIdx.x >> 5, lane = threadIdx.x & 31;
    int b = blockIdx.x * 8 + warp;
    float s0 = bn0g[0] * rsqrtf(bn0v[0] + EPSBN);
    float c0 = bn0b[0] - bn0m[0] * s0;
    int e1 = e1i[b], e2 = e2i[b], r = ri[b];
    const float4* __restrict__ Q  = (const float4*)(g_q + r * WIN);
    const float4* __restrict__ E1 = (const float4*)(Et + (size_t)e1 * D1);
    const float4* __restrict__ E2 = (const float4*)(Et + (size_t)e2 * D1);
    float acc = g_c1[lane];                 // scal1 folded into warp-reduce
    for (int u = lane; u < 100; u += 32) {
        float4 ev = (u < 50) ? E1[u] : E2[u - 50];
        float4 qv = Q[u];
        acc = fmaf(fmaf(s0, ev.x, c0), qv.x, acc);
        acc = fmaf(fmaf(s0, ev.y, c0), qv.y, acc);
        acc = fmaf(fmaf(s0, ev.z, c0), qv.z, acc);
        acc = fmaf(fmaf(s0, ev.w, c0), qv.w, acc);
    }
    for (int o = 16; o; o >>= 1) acc += __shfl_down_sync(0xffffffffu, acc, o);
    if (lane == 0)
        out[b] = tanhf(acc + g_scal0) + bias[0];
}

// ---------------- launch ------------------------------------------------
extern "C" void kernel_launch(void* const* d_in, const int* in_sizes, int n_in,
                              void* d_out, int out_size) {
    const int*   e1_idx  = (const int*)  d_in[0];
    const int*   r_idx   = (const int*)  d_in[1];
    const int*   e2_idx  = (const int*)  d_in[2];
    const float* E_table = (const float*)d_in[3];
    const float* R_table = (const float*)d_in[4];
    const float* bn0g    = (const float*)d_in[5];
    const float* bn0b    = (const float*)d_in[6];
    const float* bn0m    = (const float*)d_in[7];
    const float* bn0v    = (const float*)d_in[8];
    const float* fc1w    = (const float*)d_in[9];
    const float* fc1b    = (const float*)d_in[10];
    const float* bn1g    = (const float*)d_in[11];
    const float* bn1b    = (const float*)d_in[12];
    const float* bn1m    = (const float*)d_in[13];
    const float* bn1v    = (const float*)d_in[14];
    const float* fcw     = (const float*)d_in[15];
    const float* fcb     = (const float*)d_in[16];
    const float* bn2g    = (const float*)d_in[17];
    const float* bn2b    = (const float*)d_in[18];
    const float* bn2m    = (const float*)d_in[19];
    const float* bn2v    = (const float*)d_in[20];
    const float* fc2w    = (const float*)d_in[21];
    const float* fc2b    = (const float*)d_in[22];
    const float* bias    = (const float*)d_in[23];
    float* out = (float*)d_out;

    k1_v<<<NSPLIT * FBLK + 1, 256>>>(fcw, bn2g, bn2b, bn2m, bn2v, fc2w, fc2b, fcb);
    gemm1_krel<<<dim3(16, 9), 64>>>(R_table, fc1w, fc1b);
    kv_build<<<M1, 128>>>(bn1g, bn1b, bn1m, bn1v);
    gemm2_q<<<dim3(16, 13), 64>>>();
    k4_main<<<BATCH / 8, 256>>>(e1_idx, r_idx, e2_idx, E_table,
                                bn0g, bn0b, bn0m, bn0v, bias, out);
}